// round 3
// baseline (speedup 1.0000x reference)
#include <cuda_runtime.h>

#define TT 512
#define BB 512
#define KK 64
#define NPAIR 256
#define LOG2E 1.4426950408889634f
#define LN2   0.6931471805599453f

// scratch (device globals — no allocation)
__device__ float g_partial[BB];
__device__ int4  g_pair[NPAIR];   // {b0, b1, stop0, stop1}, sorted desc by stop
__device__ int   g_done;

__device__ __forceinline__ float ex2f_(float x){float y;asm("ex2.approx.f32 %0,%1;":"=f"(y):"f"(x));return y;}
__device__ __forceinline__ float lg2f_(float x){float y;asm("lg2.approx.f32 %0,%1;":"=f"(y):"f"(x));return y;}
__device__ __forceinline__ float rcpf_(float x){float y;asm("rcp.approx.f32 %0,%1;":"=f"(y):"f"(x));return y;}
__device__ __forceinline__ unsigned long long fma2_(unsigned long long a,unsigned long long b,unsigned long long c){
    unsigned long long d; asm("fma.rn.f32x2 %0,%1,%2,%3;":"=l"(d):"l"(a),"l"(b),"l"(c)); return d;}
__device__ __forceinline__ unsigned long long add2_(unsigned long long a,unsigned long long b){
    unsigned long long d; asm("add.rn.f32x2 %0,%1,%2;":"=l"(d):"l"(a),"l"(b)); return d;}
__device__ __forceinline__ unsigned long long pack2_(float lo,float hi){
    unsigned long long d; asm("mov.b64 %0,{%1,%2};":"=l"(d):"f"(lo),"f"(hi)); return d;}
__device__ __forceinline__ float2 unpack2_(unsigned long long v){
    float2 r; asm("mov.b64 {%0,%1},%2;":"=f"(r.x),"=f"(r.y):"l"(v)); return r;}

#define CNTB(u) ((((u)&0xFFu)!=0)+(((u)&0xFF00u)!=0)+(((u)&0xFF0000u)!=0)+(((u)&0xFF000000u)!=0))

// ---------------------------------------------------------------------------
// Prep: dtype detect (byte-count of first TT*BB bytes — safe under bool/int32/
// f32 serializations), per-batch stop index, bitonic sort desc by stop (LPT +
// equal-length pairing), emit pair table, zero the completion counter.
// ---------------------------------------------------------------------------
__global__ __launch_bounds__(1024) void prep_kernel(const unsigned char* __restrict__ mask)
{
    __shared__ int cnt_s, is4_s;
    __shared__ int stop_s[BB];
    __shared__ int bidx_s[BB];
    const int tid = threadIdx.x;

    if (tid == 0) { cnt_s = 0; g_done = 0; }
    if (tid < BB) stop_s[tid] = 0;
    __syncthreads();

    // A: count nonzero bytes in first 256KB (exactly BB nonzero <=> bool mask)
    {
        const uint4* w = (const uint4*)mask;   // 16384 uint4
        int local = 0;
        #pragma unroll
        for (int r = 0; r < 4; r++) {
            uint4 v0 = w[tid + r*4096 + 0];
            uint4 v1 = w[tid + r*4096 + 1024];
            uint4 v2 = w[tid + r*4096 + 2048];
            uint4 v3 = w[tid + r*4096 + 3072];
            local += CNTB(v0.x)+CNTB(v0.y)+CNTB(v0.z)+CNTB(v0.w);
            local += CNTB(v1.x)+CNTB(v1.y)+CNTB(v1.z)+CNTB(v1.w);
            local += CNTB(v2.x)+CNTB(v2.y)+CNTB(v2.z)+CNTB(v2.w);
            local += CNTB(v3.x)+CNTB(v3.y)+CNTB(v3.z)+CNTB(v3.w);
        }
        if (local) atomicAdd(&cnt_s, local);
    }
    __syncthreads();
    if (tid == 0) is4_s = (cnt_s == BB) ? 0 : 1;
    __syncthreads();

    // B: stops (coalesced column scans)
    if (is4_s) {
        const uint4* m4 = (const uint4*)mask;         // TT*BB words
        const int bg = tid & 127;                     // 4 b's per uint4
        const int t0 = (tid >> 7) * 64;               // 8 chunks x 64 t
        #pragma unroll 4
        for (int t = t0; t < t0 + 64; t++) {
            uint4 v = m4[t*128 + bg];
            if (v.x | v.y | v.z | v.w) {
                if (v.x) atomicMax(&stop_s[4*bg+0], t);
                if (v.y) atomicMax(&stop_s[4*bg+1], t);
                if (v.z) atomicMax(&stop_s[4*bg+2], t);
                if (v.w) atomicMax(&stop_s[4*bg+3], t);
            }
        }
    } else {
        const uint4* m1 = (const uint4*)mask;         // (TT*BB)/16 uint4
        const int bg = tid & 31;                      // 16 b's per uint4
        const int t0 = (tid >> 5) * 16;               // 32 chunks x 16 t
        #pragma unroll 4
        for (int t = t0; t < t0 + 16; t++) {
            uint4 v = m1[t*32 + bg];
            unsigned u;
            u = v.x; if (u) { if (u&0xFFu) atomicMax(&stop_s[16*bg+ 0],t); if (u&0xFF00u) atomicMax(&stop_s[16*bg+ 1],t); if (u&0xFF0000u) atomicMax(&stop_s[16*bg+ 2],t); if (u&0xFF000000u) atomicMax(&stop_s[16*bg+ 3],t); }
            u = v.y; if (u) { if (u&0xFFu) atomicMax(&stop_s[16*bg+ 4],t); if (u&0xFF00u) atomicMax(&stop_s[16*bg+ 5],t); if (u&0xFF0000u) atomicMax(&stop_s[16*bg+ 6],t); if (u&0xFF000000u) atomicMax(&stop_s[16*bg+ 7],t); }
            u = v.z; if (u) { if (u&0xFFu) atomicMax(&stop_s[16*bg+ 8],t); if (u&0xFF00u) atomicMax(&stop_s[16*bg+ 9],t); if (u&0xFF0000u) atomicMax(&stop_s[16*bg+10],t); if (u&0xFF000000u) atomicMax(&stop_s[16*bg+11],t); }
            u = v.w; if (u) { if (u&0xFFu) atomicMax(&stop_s[16*bg+12],t); if (u&0xFF00u) atomicMax(&stop_s[16*bg+13],t); if (u&0xFF0000u) atomicMax(&stop_s[16*bg+14],t); if (u&0xFF000000u) atomicMax(&stop_s[16*bg+15],t); }
        }
    }
    if (tid < BB) bidx_s[tid] = tid;
    __syncthreads();

    // C: bitonic sort (descending by stop)
    for (int k = 2; k <= BB; k <<= 1) {
        for (int jj = k >> 1; jj > 0; jj >>= 1) {
            if (tid < BB) {
                int ixj = tid ^ jj;
                if (ixj > tid) {
                    int a = stop_s[tid], b2 = stop_s[ixj];
                    bool up = ((tid & k) == 0);       // descending
                    bool sw = up ? (a < b2) : (a > b2);
                    if (sw) {
                        stop_s[tid] = b2; stop_s[ixj] = a;
                        int t1 = bidx_s[tid]; bidx_s[tid] = bidx_s[ixj]; bidx_s[ixj] = t1;
                    }
                }
            }
            __syncthreads();
        }
    }

    // D: pair table (adjacent sorted => near-equal lengths; desc order => LPT)
    if (tid < NPAIR)
        g_pair[tid] = make_int4(bidx_s[2*tid], bidx_s[2*tid+1], stop_s[2*tid], stop_s[2*tid+1]);
}

// ---------------------------------------------------------------------------
// Forward: CTA c handles batch pair (b0,b1) with stop0 >= stop1.
// Linear-domain recurrence with lagged reciprocal renormalization:
//   S_j = sum_i P_i * E_ij          (E = exp(trans), column j packed f32x2)
//   P'_j = S_j * em_j * c_prev ;    c = rcp(S_0),  C2 += lg2(S_0)  (lagged)
// Invariant: log2 alpha_j = lg2(P_j) + C2.  Final: LN2*(C2 + lg2(sum_j P_j)).
// Last-arriving CTA performs the deterministic 512->1 sum.
// ---------------------------------------------------------------------------
__global__ __launch_bounds__(KK, 4)
void crf_forward_kernel(const float* __restrict__ emits,
                        const float* __restrict__ trans,
                        const float* __restrict__ alpha0,
                        float* __restrict__ out)
{
    __shared__ float p_s[2][2][KK];   // [g][buf][j]
    __shared__ float c_s[2][2];       // [buf][g]
    __shared__ float red_s[2][2];     // [g][warp]
    __shared__ int   last_s;

    const int j = threadIdx.x;
    const int4 pr = g_pair[blockIdx.x];
    const int b0 = pr.x, b1 = pr.y, stop0 = pr.z, stop1 = pr.w;

    // E column j, packed over i-pairs
    unsigned long long tr2[KK/2];
    #pragma unroll
    for (int i = 0; i < KK/2; i++) {
        float lo = ex2f_(trans[(2*i  )*KK + j] * LOG2E);
        float hi = ex2f_(trans[(2*i+1)*KK + j] * LOG2E);
        tr2[i] = pack2_(lo, hi);
    }

    const float a0j = alpha0[j];
    float P0 = ex2f_((a0j + emits[b0*KK + j]) * LOG2E);
    float P1 = ex2f_((a0j + emits[b1*KK + j]) * LOG2E);
    float C20 = 0.f, C21 = 0.f, l0 = 0.f, l1 = 0.f;   // meaningful on j==0

    const float* e0p = emits + b0*KK + j;
    const float* e1p = emits + b1*KK + j;
    const int STRD = BB * KK;

    // depth-2 emit pipeline: em (for t), lv (raw for t+1), new load (t+2)
    float em0 = (stop0 >= 1) ? ex2f_(e0p[min(1,stop0)*STRD] * LOG2E) : 1.f;
    float em1 = (stop1 >= 1) ? ex2f_(e1p[min(1,stop1)*STRD] * LOG2E) : 1.f;
    float lv0 = e0p[min(2, stop0) * STRD];
    float lv1 = e1p[min(2, stop1) * STRD];

    p_s[0][0][j] = P0;
    p_s[1][0][j] = P1;
    if (j == 0) { c_s[0][0] = 1.f; c_s[0][1] = 1.f; }
    __syncthreads();

    int buf = 0;
    for (int t = 1; t <= stop0; t++) {
        const float ld0 = e0p[min(t+2, stop0) * STRD];   // prefetch (clamped, may be unused)
        const float ld1 = e1p[min(t+2, stop1) * STRD];
        const float c0 = c_s[buf][0];
        const float c1 = c_s[buf][1];

        // g0
        {
            const ulonglong2* p2 = (const ulonglong2*)p_s[0][buf];
            unsigned long long a0=0ull,a1=0ull,a2=0ull,a3=0ull;
            #pragma unroll
            for (int i = 0; i < 8; i++) {
                ulonglong2 v = p2[2*i], w = p2[2*i+1];
                a0 = fma2_(v.x, tr2[4*i+0], a0);
                a1 = fma2_(v.y, tr2[4*i+1], a1);
                a2 = fma2_(w.x, tr2[4*i+2], a2);
                a3 = fma2_(w.y, tr2[4*i+3], a3);
            }
            float2 f = unpack2_(add2_(add2_(a0,a1), add2_(a2,a3)));
            float S = f.x + f.y;
            P0 = S * em0 * c0;
            p_s[0][buf^1][j] = P0;
            if (j == 0) { C20 += l0; l0 = lg2f_(S); c_s[buf^1][0] = rcpf_(S); }
        }
        // g1 (uniform branch; frozen after stop1)
        if (t <= stop1) {
            const ulonglong2* p2 = (const ulonglong2*)p_s[1][buf];
            unsigned long long a0=0ull,a1=0ull,a2=0ull,a3=0ull;
            #pragma unroll
            for (int i = 0; i < 8; i++) {
                ulonglong2 v = p2[2*i], w = p2[2*i+1];
                a0 = fma2_(v.x, tr2[4*i+0], a0);
                a1 = fma2_(v.y, tr2[4*i+1], a1);
                a2 = fma2_(w.x, tr2[4*i+2], a2);
                a3 = fma2_(w.y, tr2[4*i+3], a3);
            }
            float2 f = unpack2_(add2_(add2_(a0,a1), add2_(a2,a3)));
            float S = f.x + f.y;
            P1 = S * em1 * c1;
            p_s[1][buf^1][j] = P1;
            if (j == 0) { C21 += l1; l1 = lg2f_(S); c_s[buf^1][1] = rcpf_(S); }
        }

        em0 = ex2f_(lv0 * LOG2E);  lv0 = ld0;   // off critical path
        em1 = ex2f_(lv1 * LOG2E);  lv1 = ld1;

        __syncthreads();
        buf ^= 1;
    }

    // per-b linear sum over j, then logZ
    float s0 = P0, s1 = P1;
    #pragma unroll
    for (int o = 16; o > 0; o >>= 1) {
        s0 += __shfl_xor_sync(0xffffffffu, s0, o);
        s1 += __shfl_xor_sync(0xffffffffu, s1, o);
    }
    if ((j & 31) == 0) { red_s[0][j>>5] = s0; red_s[1][j>>5] = s1; }
    __syncthreads();
    if (j == 0) {
        g_partial[b0] = LN2 * (C20 + lg2f_(red_s[0][0] + red_s[0][1]));
        g_partial[b1] = LN2 * (C21 + lg2f_(red_s[1][0] + red_s[1][1]));
        __threadfence();
        last_s = (atomicAdd(&g_done, 1) == NPAIR - 1);
    }
    __syncthreads();

    if (last_s) {                         // deterministic fixed-order 512->1 sum
        __threadfence();
        float v = 0.f;
        #pragma unroll
        for (int k = 0; k < BB/KK; k++) v += g_partial[j + k*KK];
        #pragma unroll
        for (int o = 16; o > 0; o >>= 1) v += __shfl_xor_sync(0xffffffffu, v, o);
        if ((j & 31) == 0) red_s[0][j>>5] = v;
        __syncthreads();
        if (j == 0) out[0] = red_s[0][0] + red_s[0][1];
    }
}

extern "C" void kernel_launch(void* const* d_in, const int* in_sizes, int n_in,
                              void* d_out, int out_size)
{
    const float*         emits  = 0;
    const unsigned char* mask   = 0;
    const float*         trans  = 0;
    const float*         alpha0 = 0;
    for (int i = 0; i < n_in; i++) {
        switch (in_sizes[i]) {
            case 16777216: emits  = (const float*)d_in[i];         break;
            case   262144: mask   = (const unsigned char*)d_in[i]; break;
            case     4096: trans  = (const float*)d_in[i];         break;
            case       64: alpha0 = (const float*)d_in[i];         break;
        }
    }
    prep_kernel<<<1, 1024>>>(mask);
    crf_forward_kernel<<<NPAIR, KK>>>(emits, trans, alpha0, (float*)d_out);
}

// round 4
// speedup vs baseline: 1.0331x; 1.0331x over previous
#include <cuda_runtime.h>

#define TT 512
#define BB 512
#define KK 64
#define STRD (BB*KK)
#define LOG2E 1.4426950408889634f
#define LN2   0.6931471805599453f

typedef unsigned long long ull;

// scratch (device globals — no allocation)
__device__ float g_partial[BB];
__device__ int   g_cntp[32];     // plain-stored partials, overwritten every replay

__device__ __forceinline__ float ex2f_(float x){float y;asm("ex2.approx.f32 %0,%1;":"=f"(y):"f"(x));return y;}
__device__ __forceinline__ float lg2f_(float x){float y;asm("lg2.approx.f32 %0,%1;":"=f"(y):"f"(x));return y;}
__device__ __forceinline__ float rcpf_(float x){float y;asm("rcp.approx.f32 %0,%1;":"=f"(y):"f"(x));return y;}
__device__ __forceinline__ ull fma2_(ull a,ull b,ull c){ull d;asm("fma.rn.f32x2 %0,%1,%2,%3;":"=l"(d):"l"(a),"l"(b),"l"(c));return d;}
__device__ __forceinline__ ull add2_(ull a,ull b){ull d;asm("add.rn.f32x2 %0,%1,%2;":"=l"(d):"l"(a),"l"(b));return d;}
__device__ __forceinline__ ull pack2_(float lo,float hi){ull d;asm("mov.b64 %0,{%1,%2};":"=l"(d):"f"(lo),"f"(hi));return d;}
__device__ __forceinline__ float2 unpack2_(ull v){float2 r;asm("mov.b64 {%0,%1},%2;":"=f"(r.x),"=f"(r.y):"l"(v));return r;}

#define CNTB(u) ((((u)&0xFFu)!=0)+(((u)&0xFF00u)!=0)+(((u)&0xFF0000u)!=0)+(((u)&0xFF000000u)!=0))

// ---------------------------------------------------------------------------
// Detect: 32 blocks count nonzero bytes in their 8KB slice of the first
// TT*BB bytes of the mask (safe under bool/int32/f32 serializations).
// A genuine 1-byte one-hot mask has exactly BB nonzero bytes total.
// Plain store to g_cntp — idempotent across graph replays, no zeroing needed.
// ---------------------------------------------------------------------------
__global__ __launch_bounds__(256) void detect_kernel(const unsigned char* __restrict__ m)
{
    __shared__ int w_s[8];
    const int tid = threadIdx.x;
    const uint4* w = (const uint4*)m + blockIdx.x * 512;   // 512 uint4 = 8KB
    uint4 v0 = w[tid], v1 = w[tid + 256];
    int local = CNTB(v0.x)+CNTB(v0.y)+CNTB(v0.z)+CNTB(v0.w)
              + CNTB(v1.x)+CNTB(v1.y)+CNTB(v1.z)+CNTB(v1.w);
    #pragma unroll
    for (int o = 16; o > 0; o >>= 1) local += __shfl_xor_sync(0xffffffffu, local, o);
    if ((tid & 31) == 0) w_s[tid >> 5] = local;
    __syncthreads();
    if (tid == 0) {
        int s = 0;
        #pragma unroll
        for (int k = 0; k < 8; k++) s += w_s[k];
        g_cntp[blockIdx.x] = s;
    }
}

// ---------------------------------------------------------------------------
// Forward: ONE WARP per batch element b. Lane l owns state-columns l and l+32.
// No bar.sync anywhere — p exchanged via smem + __syncwarp (double-buffered).
// Linear-domain recurrence, lagged reciprocal renormalization:
//   S_j   = sum_i P_i * E_ij        (E = exp(trans); column pairs packed f32x2 over i)
//   c_t   = rcp(S0_{t-1})  (broadcast lane0, computed during the FMA burst)
//   P'_j  = S_j * em_j * c_t ;   C2 += lg2(S0_{t-1})
// Invariant: log2 alpha_j = lg2(P_j) + C2.  Final: LN2*(C2 + lg2(sum_j P_j)).
// ---------------------------------------------------------------------------
__global__ __launch_bounds__(32)
void crf_forward_kernel(const float* __restrict__ emits,
                        const unsigned char* __restrict__ mask,
                        const float* __restrict__ trans,
                        const float* __restrict__ alpha0)
{
    __shared__ float p_s[2][KK];

    const int l = threadIdx.x;
    const int b = blockIdx.x;

    // mask dtype from detect partials (uniform, deterministic)
    int cnt = g_cntp[l];
    #pragma unroll
    for (int o = 16; o > 0; o >>= 1) cnt += __shfl_xor_sync(0xffffffffu, cnt, o);
    const bool is4 = (cnt != BB);

    // stop index for this b: strided column scan (one-hot => last nonzero)
    int stop = 0;
    if (is4) {
        const unsigned* m4 = (const unsigned*)mask;
        #pragma unroll
        for (int k = 0; k < TT / 32; k++) {
            int t = l + 32 * k;
            if (m4[t * BB + b]) stop = t;
        }
    } else {
        #pragma unroll
        for (int k = 0; k < TT / 32; k++) {
            int t = l + 32 * k;
            if (mask[t * BB + b]) stop = t;
        }
    }
    #pragma unroll
    for (int o = 16; o > 0; o >>= 1) stop = max(stop, __shfl_xor_sync(0xffffffffu, stop, o));

    // E = exp(trans): columns l and l+32, packed over i-pairs (fully register-resident)
    ull tr2a[KK / 2], tr2b[KK / 2];
    #pragma unroll
    for (int i = 0; i < KK / 2; i++) {
        tr2a[i] = pack2_(ex2f_(trans[(2*i)*KK + l     ] * LOG2E),
                         ex2f_(trans[(2*i+1)*KK + l   ] * LOG2E));
        tr2b[i] = pack2_(ex2f_(trans[(2*i)*KK + l + 32] * LOG2E),
                         ex2f_(trans[(2*i+1)*KK + l+32] * LOG2E));
    }

    const float* ep = emits + b * KK;
    float P0 = ex2f_((alpha0[l]      + ep[l]     ) * LOG2E);
    float P1 = ex2f_((alpha0[l + 32] + ep[l + 32]) * LOG2E);
    p_s[0][l]      = P0;
    p_s[0][l + 32] = P1;

    float C2 = 0.f, s0prev = 1.f;

    // emit pipeline: em (converted, for t), lv (raw, t+1), new load (t+2)
    float lv0 = ep[min(1, stop) * STRD + l];
    float lv1 = ep[min(1, stop) * STRD + l + 32];
    float em0 = ex2f_(lv0 * LOG2E);
    float em1 = ex2f_(lv1 * LOG2E);
    lv0 = ep[min(2, stop) * STRD + l];
    lv1 = ep[min(2, stop) * STRD + l + 32];
    __syncwarp();

    int buf = 0;
    for (int t = 1; t <= stop; t++) {
        const float ld0 = ep[min(t + 2, stop) * STRD + l];        // prefetch depth 2
        const float ld1 = ep[min(t + 2, stop) * STRD + l + 32];

        // lagged renormalizer — off the FMA critical path
        const float s0b = __shfl_sync(0xffffffffu, s0prev, 0);
        const float c   = rcpf_(s0b);
        const float emc0 = em0 * c, emc1 = em1 * c;
        C2 += lg2f_(s0b);                                          // lg2(1)=0 on first iter

        // matvec: both columns share one broadcast read of p
        const ulonglong2* p2 = (const ulonglong2*)p_s[buf];
        ull a0=0ull,a1=0ull,a2=0ull,a3=0ull;
        ull c0=0ull,c1=0ull,c2=0ull,c3=0ull;
        #pragma unroll
        for (int i = 0; i < 8; i++) {
            ulonglong2 v = p2[2*i], w = p2[2*i+1];
            a0 = fma2_(v.x, tr2a[4*i+0], a0);
            a1 = fma2_(v.y, tr2a[4*i+1], a1);
            a2 = fma2_(w.x, tr2a[4*i+2], a2);
            a3 = fma2_(w.y, tr2a[4*i+3], a3);
            c0 = fma2_(v.x, tr2b[4*i+0], c0);
            c1 = fma2_(v.y, tr2b[4*i+1], c1);
            c2 = fma2_(w.x, tr2b[4*i+2], c2);
            c3 = fma2_(w.y, tr2b[4*i+3], c3);
        }
        float2 fa = unpack2_(add2_(add2_(a0, a1), add2_(a2, a3)));
        float2 fc = unpack2_(add2_(add2_(c0, c1), add2_(c2, c3)));
        const float S0 = fa.x + fa.y;
        const float S1 = fc.x + fc.y;

        P0 = S0 * emc0;
        P1 = S1 * emc1;
        p_s[buf ^ 1][l]      = P0;
        p_s[buf ^ 1][l + 32] = P1;
        s0prev = S0;

        em0 = ex2f_(lv0 * LOG2E);  lv0 = ld0;                      // off critical path
        em1 = ex2f_(lv1 * LOG2E);  lv1 = ld1;

        __syncwarp();
        buf ^= 1;
    }

    // per-b logsumexp over all 64 states
    float v = P0 + P1;
    #pragma unroll
    for (int o = 16; o > 0; o >>= 1) v += __shfl_xor_sync(0xffffffffu, v, o);
    if (l == 0) g_partial[b] = LN2 * (C2 + lg2f_(v));
}

// Deterministic 512 -> 1 sum
__global__ void crf_reduce_kernel(float* __restrict__ out)
{
    __shared__ float sm[16];
    const int tid = threadIdx.x;
    float v = g_partial[tid];
    #pragma unroll
    for (int o = 16; o > 0; o >>= 1) v += __shfl_xor_sync(0xffffffffu, v, o);
    if ((tid & 31) == 0) sm[tid >> 5] = v;
    __syncthreads();
    if (tid < 16) {
        float w = sm[tid];
        #pragma unroll
        for (int o = 8; o > 0; o >>= 1) w += __shfl_xor_sync(0x0000ffffu, w, o);
        if (tid == 0) out[0] = w;
    }
}

extern "C" void kernel_launch(void* const* d_in, const int* in_sizes, int n_in,
                              void* d_out, int out_size)
{
    // Identify inputs by element count (robust to metadata ordering):
    // emits 16777216, mask 262144, trans 4096, alpha0 64.
    const float*         emits  = 0;
    const unsigned char* mask   = 0;
    const float*         trans  = 0;
    const float*         alpha0 = 0;
    for (int i = 0; i < n_in; i++) {
        switch (in_sizes[i]) {
            case 16777216: emits  = (const float*)d_in[i];         break;
            case   262144: mask   = (const unsigned char*)d_in[i]; break;
            case     4096: trans  = (const float*)d_in[i];         break;
            case       64: alpha0 = (const float*)d_in[i];         break;
        }
    }
    detect_kernel<<<32, 256>>>(mask);
    crf_forward_kernel<<<BB, 32>>>(emits, mask, trans, alpha0);
    crf_reduce_kernel<<<1, BB>>>((float*)d_out);
}

// round 6
// speedup vs baseline: 1.6518x; 1.5989x over previous
#include <cuda_runtime.h>

#define TT 512
#define BB 512
#define KK 64
#define STRD (BB*KK)
#define LOG2E 1.4426950408889634f
#define LN2   0.6931471805599453f

typedef unsigned long long ull;

// scratch (device globals — no allocation)
__device__ float g_partial[BB];
__device__ int   g_cntp[64];   // detect partials, plain-stored each replay
__device__ int   g_done;       // reset by detect block 0 each replay

__device__ __forceinline__ float ex2f_(float x){float y;asm("ex2.approx.f32 %0,%1;":"=f"(y):"f"(x));return y;}
__device__ __forceinline__ float lg2f_(float x){float y;asm("lg2.approx.f32 %0,%1;":"=f"(y):"f"(x));return y;}
__device__ __forceinline__ float rcpf_(float x){float y;asm("rcp.approx.f32 %0,%1;":"=f"(y):"f"(x));return y;}
__device__ __forceinline__ ull fma2_(ull a,ull b,ull c){ull d;asm("fma.rn.f32x2 %0,%1,%2,%3;":"=l"(d):"l"(a),"l"(b),"l"(c));return d;}
__device__ __forceinline__ ull add2_(ull a,ull b){ull d;asm("add.rn.f32x2 %0,%1,%2;":"=l"(d):"l"(a),"l"(b));return d;}
__device__ __forceinline__ ull pack2_(float lo,float hi){ull d;asm("mov.b64 %0,{%1,%2};":"=l"(d):"f"(lo),"f"(hi));return d;}
__device__ __forceinline__ float2 unpack2_(ull v){float2 r;asm("mov.b64 {%0,%1},%2;":"=f"(r.x),"=f"(r.y):"l"(v));return r;}

#define CNTB(u) ((((u)&0xFFu)!=0)+(((u)&0xFF00u)!=0)+(((u)&0xFF0000u)!=0)+(((u)&0xFF000000u)!=0))

// ---------------------------------------------------------------------------
// Detect: 64 blocks x 256 threads, one uint4 per thread over the first TT*BB
// bytes of the mask (safe under bool/int32/f32 serializations). A 1-byte
// one-hot mask has exactly BB nonzero bytes total. Plain stores: idempotent
// across graph replays. Block 0 also resets the forward completion counter.
// ---------------------------------------------------------------------------
__global__ __launch_bounds__(256) void detect_kernel(const unsigned char* __restrict__ m)
{
    __shared__ int w_s[8];
    const int tid = threadIdx.x;
    if (blockIdx.x == 0 && tid == 0) g_done = 0;
    uint4 v = ((const uint4*)m)[blockIdx.x * 256 + tid];
    int local = CNTB(v.x) + CNTB(v.y) + CNTB(v.z) + CNTB(v.w);
    #pragma unroll
    for (int o = 16; o > 0; o >>= 1) local += __shfl_xor_sync(0xffffffffu, local, o);
    if ((tid & 31) == 0) w_s[tid >> 5] = local;
    __syncthreads();
    if (tid == 0) {
        int s = 0;
        #pragma unroll
        for (int k = 0; k < 8; k++) s += w_s[k];
        g_cntp[blockIdx.x] = s;
    }
}

// ---------------------------------------------------------------------------
// Forward: one CTA (64 threads = 2 warps) per batch element b; thread j owns
// state-column j. Linear-domain recurrence with lagged reciprocal renorm:
//   S_j  = sum_i P_i * E_ij    (E = exp(trans), column j packed f32x2 over i)
//   P'_j = S_j * em_j * c  ;  c = rcp(S0 of previous step)
//   C2 += lC; lC = lg2(S0)    (LAGGED — C2 must equal lg2 of applied divisor)
// Invariant: log2 alpha_j = lg2(P_j) + C2 (exact).
// Final per-b: LN2 * (C2 + lg2(sum_j P_j)). Last-arriving CTA does 512->1 sum.
// ---------------------------------------------------------------------------
__global__ __launch_bounds__(KK, 8)
void crf_forward_kernel(const float* __restrict__ emits,
                        const unsigned char* __restrict__ mask,
                        const float* __restrict__ trans,
                        const float* __restrict__ alpha0,
                        float* __restrict__ out)
{
    __shared__ float p_s[2][KK];
    __shared__ float c_s[2];
    __shared__ float red_s[2];
    __shared__ int   stop_sh;
    __shared__ int   is4_sh;
    __shared__ int   last_s;

    const int j = threadIdx.x;
    const int b = blockIdx.x;

    if (j == 0) stop_sh = 0;

    // mask dtype: sum the 64 detect partials (warp0 lanes load one each)
    if (j < 32) {
        int c0 = g_cntp[j] + g_cntp[j + 32];
        #pragma unroll
        for (int o = 16; o > 0; o >>= 1) c0 += __shfl_xor_sync(0xffffffffu, c0, o);
        if (j == 0) is4_sh = (c0 != BB);
    }
    __syncthreads();
    const bool is4 = is4_sh;

    // stop index: one-hot => exactly one thread fires the atomic
    if (is4) {
        const unsigned* m4 = (const unsigned*)mask;
        #pragma unroll
        for (int k = 0; k < TT / KK; k++) {
            int t = j + KK * k;
            if (m4[t * BB + b]) atomicMax(&stop_sh, t);
        }
    } else {
        #pragma unroll
        for (int k = 0; k < TT / KK; k++) {
            int t = j + KK * k;
            if (mask[t * BB + b]) atomicMax(&stop_sh, t);
        }
    }

    // E = exp(trans) column j, packed over i-pairs (register-resident)
    ull tr2[KK / 2];
    #pragma unroll
    for (int m = 0; m < KK / 2; m++)
        tr2[m] = pack2_(ex2f_(trans[(2*m  )*KK + j] * LOG2E),
                        ex2f_(trans[(2*m+1)*KK + j] * LOG2E));

    __syncthreads();
    const int stop = stop_sh;   // uniform

    const float* ep = emits + b * KK + j;
    float P = ex2f_((alpha0[j] + ep[0]) * LOG2E);
    p_s[0][j] = P;
    if (j == 0) c_s[0] = 1.0f;
    float C2 = 0.f, lC = 0.f;

    // emit pipeline: em = converted emit(t), lv = raw emit(t+1), pld -> emit(t+2)
    float em = ex2f_(ep[min(1, stop) * STRD] * LOG2E);
    float lv = ep[min(2, stop) * STRD];
    const float* pld = ep + (long)min(3, stop) * STRD;

    __syncthreads();

    int buf = 0;
    for (int t = 1; t <= stop; t++) {
        const float ld = *pld;                       // prefetch emit(t+2)
        if (t + 3 <= stop) pld += STRD;              // predicated advance

        const float emc = em * c_s[buf];             // LDS + 1 mul, off burst path

        const ulonglong2* p2 = (const ulonglong2*)p_s[buf];
        ull a0 = 0ull, a1 = 0ull, a2 = 0ull, a3 = 0ull;
        #pragma unroll
        for (int i = 0; i < 8; i++) {
            ulonglong2 v = p2[2*i], w = p2[2*i+1];
            a0 = fma2_(v.x, tr2[4*i+0], a0);
            a1 = fma2_(v.y, tr2[4*i+1], a1);
            a2 = fma2_(w.x, tr2[4*i+2], a2);
            a3 = fma2_(w.y, tr2[4*i+3], a3);
        }
        float2 f = unpack2_(add2_(add2_(a0, a1), add2_(a2, a3)));
        const float S = f.x + f.y;

        P = S * emc;
        p_s[buf ^ 1][j] = P;
        if (j == 0) {                                // S here IS S_0
            c_s[buf ^ 1] = rcpf_(S);
            C2 += lC;                                // LAGGED: add lg2(S_{t-1})
            lC = lg2f_(S);                           //        stage lg2(S_t)
        }

        em = ex2f_(lv * LOG2E);                      // off-chain MUFU
        lv = ld;

        __syncthreads();                             // one barrier per step
        buf ^= 1;
    }

    // per-b sum over states -> logZ_b
    float v = P;
    #pragma unroll
    for (int o = 16; o > 0; o >>= 1) v += __shfl_xor_sync(0xffffffffu, v, o);
    if ((j & 31) == 0) red_s[j >> 5] = v;
    __syncthreads();
    if (j == 0) {
        g_partial[b] = LN2 * (C2 + lg2f_(red_s[0] + red_s[1]));
        __threadfence();
        last_s = (atomicAdd(&g_done, 1) == BB - 1);
    }
    __syncthreads();

    if (last_s) {                                    // deterministic 512->1 sum
        __threadfence();
        float s = 0.f;
        #pragma unroll
        for (int k = 0; k < BB / KK; k++) s += g_partial[j + k * KK];
        #pragma unroll
        for (int o = 16; o > 0; o >>= 1) s += __shfl_xor_sync(0xffffffffu, s, o);
        if ((j & 31) == 0) red_s[j >> 5] = s;
        __syncthreads();
        if (j == 0) out[0] = red_s[0] + red_s[1];
    }
}

extern "C" void kernel_launch(void* const* d_in, const int* in_sizes, int n_in,
                              void* d_out, int out_size)
{
    // Identify inputs by element count (robust to metadata ordering):
    // emits 16777216, mask 262144, trans 4096, alpha0 64.
    const float*         emits  = 0;
    const unsigned char* mask   = 0;
    const float*         trans  = 0;
    const float*         alpha0 = 0;
    for (int i = 0; i < n_in; i++) {
        switch (in_sizes[i]) {
            case 16777216: emits  = (const float*)d_in[i];         break;
            case   262144: mask   = (const unsigned char*)d_in[i]; break;
            case     4096: trans  = (const float*)d_in[i];         break;
            case       64: alpha0 = (const float*)d_in[i];         break;
        }
    }
    detect_kernel<<<64, 256>>>(mask);
    crf_forward_kernel<<<BB, KK>>>(emits, mask, trans, alpha0, (float*)d_out);
}

// round 7
// speedup vs baseline: 1.9430x; 1.1763x over previous
#include <cuda_runtime.h>

#define TT 512
#define BB 512
#define KK 64
#define STRD (BB*KK)
#define LOG2E 1.4426950408889634f
#define LN2   0.6931471805599453f

typedef unsigned long long ull;

// scratch (device globals — no allocation)
__device__ float g_partial[BB];
__device__ int   g_cntp[64];   // detect partials, plain-stored each replay
__device__ int   g_done;       // reset by detect block 0 each replay

__device__ __forceinline__ float ex2f_(float x){float y;asm("ex2.approx.f32 %0,%1;":"=f"(y):"f"(x));return y;}
__device__ __forceinline__ float lg2f_(float x){float y;asm("lg2.approx.f32 %0,%1;":"=f"(y):"f"(x));return y;}
__device__ __forceinline__ float rcpf_(float x){float y;asm("rcp.approx.f32 %0,%1;":"=f"(y):"f"(x));return y;}
__device__ __forceinline__ ull fma2_(ull a,ull b,ull c){ull d;asm("fma.rn.f32x2 %0,%1,%2,%3;":"=l"(d):"l"(a),"l"(b),"l"(c));return d;}
__device__ __forceinline__ ull add2_(ull a,ull b){ull d;asm("add.rn.f32x2 %0,%1,%2;":"=l"(d):"l"(a),"l"(b));return d;}
__device__ __forceinline__ ull pack2_(float lo,float hi){ull d;asm("mov.b64 %0,{%1,%2};":"=l"(d):"f"(lo),"f"(hi));return d;}
__device__ __forceinline__ float2 unpack2_(ull v){float2 r;asm("mov.b64 {%0,%1},%2;":"=f"(r.x),"=f"(r.y):"l"(v));return r;}

#define CNTB(u) ((((u)&0xFFu)!=0)+(((u)&0xFF00u)!=0)+(((u)&0xFF0000u)!=0)+(((u)&0xFF000000u)!=0))

// ---------------------------------------------------------------------------
// Detect: 64 blocks x 256 threads, one uint4 per thread over the first TT*BB
// bytes of the mask (safe under bool/int32/f32 serializations). A 1-byte
// one-hot mask has exactly BB nonzero bytes total. Plain stores: idempotent
// across graph replays. Block 0 also resets the forward completion counter.
// ---------------------------------------------------------------------------
__global__ __launch_bounds__(256) void detect_kernel(const unsigned char* __restrict__ m)
{
    __shared__ int w_s[8];
    const int tid = threadIdx.x;
    if (blockIdx.x == 0 && tid == 0) g_done = 0;
    uint4 v = ((const uint4*)m)[blockIdx.x * 256 + tid];
    int local = CNTB(v.x) + CNTB(v.y) + CNTB(v.z) + CNTB(v.w);
    #pragma unroll
    for (int o = 16; o > 0; o >>= 1) local += __shfl_xor_sync(0xffffffffu, local, o);
    if ((tid & 31) == 0) w_s[tid >> 5] = local;
    __syncthreads();
    if (tid == 0) {
        int s = 0;
        #pragma unroll
        for (int k = 0; k < 8; k++) s += w_s[k];
        g_cntp[blockIdx.x] = s;
    }
}

// ---------------------------------------------------------------------------
// Forward: one CTA (64 threads = 2 warps) per batch element b; thread j owns
// state-column j. Linear-domain recurrence, REGISTER-LOCAL pivot renorm:
//   S_j  = sum_i P_i * E_ij      (E = exp(trans), column j packed f32x2 over i)
//   c    = rcp(P_0^{t-1})        (every thread reads P_0 in its own matvec LDS
//                                 -> computed redundantly, no smem round trip)
//   P'_j = S_j * em_j * c ;  C2 += lg2(P_0^{t-1})   (both hidden under burst)
// Invariant: log2 alpha_j = lg2(P_j) + C2 (exact, no lag by construction).
// Final per-b: LN2 * (C2 + lg2(sum_j P_j)). Last-arriving CTA does 512->1 sum.
// ---------------------------------------------------------------------------
__global__ __launch_bounds__(KK, 8)
void crf_forward_kernel(const float* __restrict__ emits,
                        const unsigned char* __restrict__ mask,
                        const float* __restrict__ trans,
                        const float* __restrict__ alpha0,
                        float* __restrict__ out)
{
    __shared__ float p_s[2][KK];
    __shared__ float red_s[2];
    __shared__ int   stop_sh;
    __shared__ int   is4_sh;
    __shared__ int   last_s;

    const int j = threadIdx.x;
    const int b = blockIdx.x;

    if (j == 0) stop_sh = 0;

    // mask dtype: sum the 64 detect partials (warp0 lanes load one each)
    if (j < 32) {
        int c0 = g_cntp[j] + g_cntp[j + 32];
        #pragma unroll
        for (int o = 16; o > 0; o >>= 1) c0 += __shfl_xor_sync(0xffffffffu, c0, o);
        if (j == 0) is4_sh = (c0 != BB);
    }
    __syncthreads();
    const bool is4 = is4_sh;

    // stop index: one-hot => exactly one thread fires the atomic
    if (is4) {
        const unsigned* m4 = (const unsigned*)mask;
        #pragma unroll
        for (int k = 0; k < TT / KK; k++) {
            int t = j + KK * k;
            if (m4[t * BB + b]) atomicMax(&stop_sh, t);
        }
    } else {
        #pragma unroll
        for (int k = 0; k < TT / KK; k++) {
            int t = j + KK * k;
            if (mask[t * BB + b]) atomicMax(&stop_sh, t);
        }
    }

    // E = exp(trans) column j, packed over i-pairs (register-resident)
    ull tr2[KK / 2];
    #pragma unroll
    for (int m = 0; m < KK / 2; m++)
        tr2[m] = pack2_(ex2f_(trans[(2*m  )*KK + j] * LOG2E),
                        ex2f_(trans[(2*m+1)*KK + j] * LOG2E));

    __syncthreads();
    const int stop = stop_sh;   // uniform

    const float* ep = emits + b * KK + j;
    float P = ex2f_((alpha0[j] + ep[0]) * LOG2E);
    p_s[0][j] = P;
    float C2 = 0.f;

    // emit pipeline depth 4: em = converted emit(t); r1,r2,r3 = raw emit(t+1..t+3)
    float em = ex2f_(ep[min(1, stop) * STRD] * LOG2E);
    float r1 = ep[min(2, stop) * STRD];
    float r2 = ep[min(3, stop) * STRD];
    float r3 = ep[min(4, stop) * STRD];
    const float* pld = ep + (long)min(5, stop) * STRD;

    __syncthreads();

    int buf = 0;
    for (int t = 1; t <= stop; t++) {
        const float ld = *pld;                       // prefetch emit(t+4): ~4 steps of slack
        if (t + 5 <= stop) pld += STRD;              // predicated advance

        const ulonglong2* p2 = (const ulonglong2*)p_s[buf];

        // first LDS.128 carries P_0 in its low float -> pivot renormalizer.
        ulonglong2 v0 = p2[0];
        const float p0prev = unpack2_(v0.x).x;
        const float c   = rcpf_(p0prev);             // hidden under the burst
        C2 += lg2f_(p0prev);                         // hidden under the burst
        const float emc = em * c;

        ull a0 = fma2_(v0.x, tr2[0], 0ull);
        ull a1 = fma2_(v0.y, tr2[1], 0ull);
        ull a2 = 0ull, a3 = 0ull;
        {
            ulonglong2 w0 = p2[1];
            a2 = fma2_(w0.x, tr2[2], a2);
            a3 = fma2_(w0.y, tr2[3], a3);
        }
        #pragma unroll
        for (int i = 1; i < 8; i++) {
            ulonglong2 v = p2[2*i], w = p2[2*i+1];
            a0 = fma2_(v.x, tr2[4*i+0], a0);
            a1 = fma2_(v.y, tr2[4*i+1], a1);
            a2 = fma2_(w.x, tr2[4*i+2], a2);
            a3 = fma2_(w.y, tr2[4*i+3], a3);
        }
        float2 f = unpack2_(add2_(add2_(a0, a1), add2_(a2, a3)));
        const float S = f.x + f.y;

        P = S * emc;
        p_s[buf ^ 1][j] = P;

        em = ex2f_(r1 * LOG2E);                      // off-chain MUFU
        r1 = r2; r2 = r3; r3 = ld;

        __syncthreads();                             // one barrier per step
        buf ^= 1;
    }

    // per-b sum over states -> logZ_b
    float v = P;
    #pragma unroll
    for (int o = 16; o > 0; o >>= 1) v += __shfl_xor_sync(0xffffffffu, v, o);
    if ((j & 31) == 0) red_s[j >> 5] = v;
    __syncthreads();
    if (j == 0) {
        g_partial[b] = LN2 * (C2 + lg2f_(red_s[0] + red_s[1]));
        __threadfence();
        last_s = (atomicAdd(&g_done, 1) == BB - 1);
    }
    __syncthreads();

    if (last_s) {                                    // deterministic 512->1 sum
        __threadfence();
        float s = 0.f;
        #pragma unroll
        for (int k = 0; k < BB / KK; k++) s += g_partial[j + k * KK];
        #pragma unroll
        for (int o = 16; o > 0; o >>= 1) s += __shfl_xor_sync(0xffffffffu, s, o);
        if ((j & 31) == 0) red_s[j >> 5] = s;
        __syncthreads();
        if (j == 0) out[0] = red_s[0] + red_s[1];
    }
}

extern "C" void kernel_launch(void* const* d_in, const int* in_sizes, int n_in,
                              void* d_out, int out_size)
{
    // Identify inputs by element count (robust to metadata ordering):
    // emits 16777216, mask 262144, trans 4096, alpha0 64.
    const float*         emits  = 0;
    const unsigned char* mask   = 0;
    const float*         trans  = 0;
    const float*         alpha0 = 0;
    for (int i = 0; i < n_in; i++) {
        switch (in_sizes[i]) {
            case 16777216: emits  = (const float*)d_in[i];         break;
            case   262144: mask   = (const unsigned char*)d_in[i]; break;
            case     4096: trans  = (const float*)d_in[i];         break;
            case       64: alpha0 = (const float*)d_in[i];         break;
        }
    }
    detect_kernel<<<64, 256>>>(mask);
    crf_forward_kernel<<<BB, KK>>>(emits, mask, trans, alpha0, (float*)d_out);
}

// round 8
// speedup vs baseline: 2.0390x; 1.0494x over previous
#include <cuda_runtime.h>

#define TT 512
#define BB 512
#define KK 64
#define STRD (BB*KK)
#define LOG2E 1.4426950408889634f
#define LN2   0.6931471805599453f

typedef unsigned long long ull;

// scratch (device globals — no allocation)
__device__ float g_partial[BB];
__device__ int   g_cntp[64];   // detect partials, plain-stored each replay
__device__ int   g_done;       // reset by detect block 0 each replay

__device__ __forceinline__ float ex2f_(float x){float y;asm("ex2.approx.f32 %0,%1;":"=f"(y):"f"(x));return y;}
__device__ __forceinline__ float lg2f_(float x){float y;asm("lg2.approx.f32 %0,%1;":"=f"(y):"f"(x));return y;}
__device__ __forceinline__ float rcpf_(float x){float y;asm("rcp.approx.f32 %0,%1;":"=f"(y):"f"(x));return y;}
__device__ __forceinline__ ull fma2_(ull a,ull b,ull c){ull d;asm("fma.rn.f32x2 %0,%1,%2,%3;":"=l"(d):"l"(a),"l"(b),"l"(c));return d;}
__device__ __forceinline__ ull add2_(ull a,ull b){ull d;asm("add.rn.f32x2 %0,%1,%2;":"=l"(d):"l"(a),"l"(b));return d;}
__device__ __forceinline__ ull pack2_(float lo,float hi){ull d;asm("mov.b64 %0,{%1,%2};":"=l"(d):"f"(lo),"f"(hi));return d;}
__device__ __forceinline__ float2 unpack2_(ull v){float2 r;asm("mov.b64 {%0,%1},%2;":"=f"(r.x),"=f"(r.y):"l"(v));return r;}

#define CNTB(u) ((((u)&0xFFu)!=0)+(((u)&0xFF00u)!=0)+(((u)&0xFF0000u)!=0)+(((u)&0xFF000000u)!=0))

// ---------------------------------------------------------------------------
// Detect: 64 blocks x 256 threads, one uint4 per thread over the first TT*BB
// bytes of the mask (safe under bool/int32/f32 serializations). A 1-byte
// one-hot mask has exactly BB nonzero bytes total. Plain stores: idempotent
// across graph replays. Block 0 also resets the forward completion counter.
// ---------------------------------------------------------------------------
__global__ __launch_bounds__(256) void detect_kernel(const unsigned char* __restrict__ m)
{
    __shared__ int w_s[8];
    const int tid = threadIdx.x;
    if (blockIdx.x == 0 && tid == 0) g_done = 0;
    uint4 v = ((const uint4*)m)[blockIdx.x * 256 + tid];
    int local = CNTB(v.x) + CNTB(v.y) + CNTB(v.z) + CNTB(v.w);
    #pragma unroll
    for (int o = 16; o > 0; o >>= 1) local += __shfl_xor_sync(0xffffffffu, local, o);
    if ((tid & 31) == 0) w_s[tid >> 5] = local;
    __syncthreads();
    if (tid == 0) {
        int s = 0;
        #pragma unroll
        for (int k = 0; k < 8; k++) s += w_s[k];
        g_cntp[blockIdx.x] = s;
    }
}

// ---------------------------------------------------------------------------
// Forward: one CTA (64 threads = 2 warps) per batch element b; thread j owns
// state-column j. Linear-domain recurrence, register-local pivot renorm:
//   S_j  = sum_i P_i * E_ij      (E = exp(trans), column j packed f32x2 over i)
//   c    = rcp(P_0^{t-1})        (P_0 read from the thread's own first LDS.128)
//   P'_j = S_j * em_j * c ;  C2 += lg2(P_0^{t-1})   (both hidden under burst)
// Invariant: log2 alpha_j = lg2(P_j) + C2 (exact).
// t-loop unrolled x2 with STATIC buffer roles: compile-time smem offsets,
// no buf^=1, half the branch overhead. One __syncthreads per step.
// Final per-b: LN2 * (C2 + lg2(sum_j P_j)). Last-arriving CTA does 512->1 sum.
// ---------------------------------------------------------------------------
__global__ __launch_bounds__(KK, 8)
void crf_forward_kernel(const float* __restrict__ emits,
                        const unsigned char* __restrict__ mask,
                        const float* __restrict__ trans,
                        const float* __restrict__ alpha0,
                        float* __restrict__ out)
{
    __shared__ float p_s[2][KK];
    __shared__ float red_s[2];
    __shared__ int   stop_sh;
    __shared__ int   is4_sh;
    __shared__ int   last_s;

    const int j = threadIdx.x;
    const int b = blockIdx.x;

    if (j == 0) stop_sh = 0;

    // mask dtype: sum the 64 detect partials (warp0 lanes load one each)
    if (j < 32) {
        int c0 = g_cntp[j] + g_cntp[j + 32];
        #pragma unroll
        for (int o = 16; o > 0; o >>= 1) c0 += __shfl_xor_sync(0xffffffffu, c0, o);
        if (j == 0) is4_sh = (c0 != BB);
    }
    __syncthreads();
    const bool is4 = is4_sh;

    // stop index: one-hot => exactly one thread fires the atomic
    if (is4) {
        const unsigned* m4 = (const unsigned*)mask;
        #pragma unroll
        for (int k = 0; k < TT / KK; k++) {
            int t = j + KK * k;
            if (m4[t * BB + b]) atomicMax(&stop_sh, t);
        }
    } else {
        #pragma unroll
        for (int k = 0; k < TT / KK; k++) {
            int t = j + KK * k;
            if (mask[t * BB + b]) atomicMax(&stop_sh, t);
        }
    }

    // E = exp(trans) column j, packed over i-pairs (register-resident)
    ull tr2[KK / 2];
    #pragma unroll
    for (int m = 0; m < KK / 2; m++)
        tr2[m] = pack2_(ex2f_(trans[(2*m  )*KK + j] * LOG2E),
                        ex2f_(trans[(2*m+1)*KK + j] * LOG2E));

    __syncthreads();
    const int stop = stop_sh;   // uniform

    const float* ep = emits + b * KK + j;
    float P = ex2f_((alpha0[j] + ep[0]) * LOG2E);
    p_s[0][j] = P;
    float C2 = 0.f;

    // emit pipeline depth 4: em = converted emit(t); r1,r2,r3 = raw emit(t+1..t+3)
    float em = ex2f_(ep[min(1, stop) * STRD] * LOG2E);
    float r1 = ep[min(2, stop) * STRD];
    float r2 = ep[min(3, stop) * STRD];
    float r3 = ep[min(4, stop) * STRD];
    const float* pld = ep + (long)min(5, stop) * STRD;

    __syncthreads();

    // One recurrence step: read p_s[RB], write p_s[WB]. Static buffer indices.
#define CRF_STEP(RB, WB, TCUR)                                                 \
    {                                                                          \
        const float ld = *pld;                       /* prefetch emit(t+4) */  \
        if ((TCUR) + 5 <= stop) pld += STRD;                                   \
        const ulonglong2* p2 = (const ulonglong2*)p_s[RB];                     \
        ulonglong2 v0 = p2[0];                                                 \
        const float p0prev = unpack2_(v0.x).x;                                 \
        const float c = rcpf_(p0prev);               /* hidden under burst */  \
        C2 += lg2f_(p0prev);                                                   \
        const float emc = em * c;                                              \
        ull a0 = fma2_(v0.x, tr2[0], 0ull);                                    \
        ull a1 = fma2_(v0.y, tr2[1], 0ull);                                    \
        ulonglong2 w0 = p2[1];                                                 \
        ull a2 = fma2_(w0.x, tr2[2], 0ull);                                    \
        ull a3 = fma2_(w0.y, tr2[3], 0ull);                                    \
        _Pragma("unroll")                                                      \
        for (int i = 1; i < 8; i++) {                                          \
            ulonglong2 v = p2[2*i], w = p2[2*i+1];                             \
            a0 = fma2_(v.x, tr2[4*i+0], a0);                                   \
            a1 = fma2_(v.y, tr2[4*i+1], a1);                                   \
            a2 = fma2_(w.x, tr2[4*i+2], a2);                                   \
            a3 = fma2_(w.y, tr2[4*i+3], a3);                                   \
        }                                                                      \
        float2 f = unpack2_(add2_(add2_(a0, a1), add2_(a2, a3)));              \
        const float S = f.x + f.y;                                             \
        P = S * emc;                                                           \
        p_s[WB][j] = P;                                                        \
        em = ex2f_(r1 * LOG2E);                      /* off-chain MUFU */      \
        r1 = r2; r2 = r3; r3 = ld;                                             \
        __syncthreads();                                                       \
    }

    int t = 1;
    for (; t + 1 <= stop; t += 2) {
        CRF_STEP(0, 1, t)
        CRF_STEP(1, 0, t + 1)
    }
    if (t <= stop) CRF_STEP(0, 1, t)
#undef CRF_STEP

    // per-b sum over states -> logZ_b
    float v = P;
    #pragma unroll
    for (int o = 16; o > 0; o >>= 1) v += __shfl_xor_sync(0xffffffffu, v, o);
    if ((j & 31) == 0) red_s[j >> 5] = v;
    __syncthreads();
    if (j == 0) {
        g_partial[b] = LN2 * (C2 + lg2f_(red_s[0] + red_s[1]));
        __threadfence();
        last_s = (atomicAdd(&g_done, 1) == BB - 1);
    }
    __syncthreads();

    if (last_s) {                                    // deterministic 512->1 sum
        __threadfence();
        float s = 0.f;
        #pragma unroll
        for (int k = 0; k < BB / KK; k++) s += g_partial[j + k * KK];
        #pragma unroll
        for (int o = 16; o > 0; o >>= 1) s += __shfl_xor_sync(0xffffffffu, s, o);
        if ((j & 31) == 0) red_s[j >> 5] = s;
        __syncthreads();
        if (j == 0) out[0] = red_s[0] + red_s[1];
    }
}

extern "C" void kernel_launch(void* const* d_in, const int* in_sizes, int n_in,
                              void* d_out, int out_size)
{
    // Identify inputs by element count (robust to metadata ordering):
    // emits 16777216, mask 262144, trans 4096, alpha0 64.
    const float*         emits  = 0;
    const unsigned char* mask   = 0;
    const float*         trans  = 0;
    const float*         alpha0 = 0;
    for (int i = 0; i < n_in; i++) {
        switch (in_sizes[i]) {
            case 16777216: emits  = (const float*)d_in[i];         break;
            case   262144: mask   = (const unsigned char*)d_in[i]; break;
            case     4096: trans  = (const float*)d_in[i];         break;
            case       64: alpha0 = (const float*)d_in[i];         break;
        }
    }
    detect_kernel<<<64, 256>>>(mask);
    crf_forward_kernel<<<BB, KK>>>(emits, mask, trans, alpha0, (float*)d_out);
}